// round 14
// baseline (speedup 1.0000x reference)
#include <cuda_runtime.h>
#include <cuda_bf16.h>
#include <cstdint>
#include <cstddef>

// ---------------------------------------------------------------------------
// FullGapModel, specialized: D = 128, P = 1, zeta = 2.
// out[s] = sum_{atoms a in s} ps_a^T Q ps_a / ||ps_a||^2,
//   Q = sum_m w[seg_sup[m]] * sp_m sp_m^T  (128x128, symmetric).
// Main kernel: bf16 mma.sync (m16n8k16) GEMM Y = H * Q with Q split into
// bf16 hi+lo (both accumulated into the same f32 C), A-side error
// compensation in the epilogue (val = dot(2*ps - h, Y) / ||ps||^2, ps
// re-read from global/L2, h from smem). 2 CTAs/SM for phase overlap.
// ---------------------------------------------------------------------------

#define DIMS 128
constexpr int TILE_M     = 128;     // atoms per CTA tile
constexpr int THREADS_B  = 512;     // 16 warps: 4 (m) x 4 (n)
constexpr int MAX_ATOMS  = 131072;  // >= N = 100000
constexpr int QP_BLOCKS  = 80;
constexpr int MAX_STRUCT = 8192;    // >= S = 2000

__device__ float    g_Qpart[QP_BLOCKS][DIMS * DIMS];
__device__ uint32_t g_Bhi_pack[8192];   // bf16x2 fragment-packed Q hi
__device__ uint32_t g_Blo_pack[8192];   // bf16x2 fragment-packed Q lo
__device__ float    g_atomval[MAX_ATOMS];
__device__ int      g_start[MAX_STRUCT + 1];

// ---------------------------------------------------------------------------
// Kernel A1: partial Q over M-chunks. Thread owns 8x8 register tile of Q.
// ---------------------------------------------------------------------------
__global__ __launch_bounds__(256) void compute_Q_partial(
    const float* __restrict__ sp,
    const float* __restrict__ weights,
    const int*   __restrict__ supseg,
    int M)
{
    __shared__ float srow[8][DIMS];
    __shared__ float sw[8];

    const int chunk = (M + QP_BLOCKS - 1) / QP_BLOCKS;
    const int m_lo = blockIdx.x * chunk;
    const int m_hi = min(M, m_lo + chunk);

    const int i0 = (threadIdx.x >> 4) * 8;
    const int j0 = (threadIdx.x & 15) * 8;

    float acc[8][8];
    #pragma unroll
    for (int a = 0; a < 8; a++)
        #pragma unroll
        for (int b = 0; b < 8; b++) acc[a][b] = 0.f;

    for (int m0 = m_lo; m0 < m_hi; m0 += 8) {
        const int rows = min(8, m_hi - m0);
        __syncthreads();
        for (int idx = threadIdx.x; idx < rows * DIMS; idx += 256)
            srow[idx >> 7][idx & 127] = sp[(size_t)m0 * DIMS + idx];
        if (threadIdx.x < rows)
            sw[threadIdx.x] = weights[supseg[m0 + threadIdx.x]];
        __syncthreads();

        #pragma unroll 8
        for (int u = 0; u < rows; u++) {
            float si[8], sj[8];
            *reinterpret_cast<float4*>(&si[0]) = *reinterpret_cast<float4*>(&srow[u][i0]);
            *reinterpret_cast<float4*>(&si[4]) = *reinterpret_cast<float4*>(&srow[u][i0 + 4]);
            *reinterpret_cast<float4*>(&sj[0]) = *reinterpret_cast<float4*>(&srow[u][j0]);
            *reinterpret_cast<float4*>(&sj[4]) = *reinterpret_cast<float4*>(&srow[u][j0 + 4]);
            const float wu = sw[u];
            #pragma unroll
            for (int a = 0; a < 8; a++) {
                const float siw = wu * si[a];
                #pragma unroll
                for (int b = 0; b < 8; b++)
                    acc[a][b] = fmaf(siw, sj[b], acc[a][b]);
            }
        }
    }

    float* dst = g_Qpart[blockIdx.x];
    #pragma unroll
    for (int a = 0; a < 8; a++)
        #pragma unroll
        for (int b = 0; b < 8; b += 4)
            *reinterpret_cast<float4*>(&dst[(i0 + a) * DIMS + j0 + b]) =
                *reinterpret_cast<float4*>(&acc[a][b]);
}

// ---------------------------------------------------------------------------
// Kernel A2: reduce partials; emit bf16 hi/lo Q in mma fragment-packed order.
// For element (n, k): B-frag of tile (t = n/8, u = k/16) at lane
// l = (n%8)*4 + ((k%8)>>1), reg r = (k%16)/8, halfword = k&1.
// ---------------------------------------------------------------------------
__global__ void reduce_Q()
{
    const int idx = blockIdx.x * blockDim.x + threadIdx.x;   // 0..16383
    const int n = idx >> 7, k = idx & 127;
    float s = 0.f;
    #pragma unroll 8
    for (int p = 0; p < QP_BLOCKS; p++)
        s += g_Qpart[p][idx];

    const __nv_bfloat16 hi = __float2bfloat16_rn(s);
    const __nv_bfloat16 lo = __float2bfloat16_rn(s - __bfloat162float(hi));

    const int u = k >> 4, t = n >> 3;
    const int g = n & 7, kk = k & 15;
    const int r = kk >> 3, tg = (kk & 7) >> 1, half = kk & 1;
    const int u32idx = ((u * 16 + t) * 32 + (g * 4 + tg)) * 2 + r;

    reinterpret_cast<__nv_bfloat16*>(g_Bhi_pack)[u32idx * 2 + half] = hi;
    reinterpret_cast<__nv_bfloat16*>(g_Blo_pack)[u32idx * 2 + half] = lo;
}

// ---------------------------------------------------------------------------
// Kernel D: structure boundaries from the sorted atom_segments array.
// ---------------------------------------------------------------------------
__global__ void mark_starts(const int* __restrict__ aseg, int N, int S)
{
    const int i = blockIdx.x * blockDim.x + threadIdx.x;
    if (i >= N) return;
    const int cur = aseg[i];
    const int prev = (i == 0) ? -1 : aseg[i - 1];
    for (int s = prev + 1; s <= cur; s++) g_start[s] = i;
    if (i == N - 1)
        for (int s = cur + 1; s <= S; s++) g_start[s] = N;
}

// ---------------------------------------------------------------------------
// Kernel B: HMMA quadratic form. 2 CTAs/SM (no E buffer, <=64 regs).
// smem: A (bf16, 128 x stride136), Bhi/Blo packed (32KB each),
//       spart[128][4], inv[128]. ~101 KB total.
// ---------------------------------------------------------------------------
constexpr int A_STRIDE  = 136;                         // bf16 units
constexpr int OFF_A     = 0;                           // 128*136*2 = 34816
constexpr int OFF_BHI   = 34816;                       // 32768 B
constexpr int OFF_BLO   = OFF_BHI + 32768;             // 67584, 32768 B
constexpr int OFF_SPART = OFF_BLO + 32768;             // 100352, 2048 B
constexpr int OFF_INV   = OFF_SPART + 2048;            // 102400, 512 B
constexpr int SMEM_TOTAL_B = OFF_INV + 512;            // 102912 B

__device__ __forceinline__ void mma_bf16(float* d, const uint32_t* a,
                                         uint32_t b0, uint32_t b1) {
    asm volatile(
        "mma.sync.aligned.m16n8k16.row.col.f32.bf16.bf16.f32 "
        "{%0,%1,%2,%3}, {%4,%5,%6,%7}, {%8,%9}, {%0,%1,%2,%3};"
        : "+f"(d[0]), "+f"(d[1]), "+f"(d[2]), "+f"(d[3])
        : "r"(a[0]), "r"(a[1]), "r"(a[2]), "r"(a[3]), "r"(b0), "r"(b1));
}

__device__ __forceinline__ void ldsm_x4(uint32_t* r, uint32_t addr) {
    asm volatile(
        "ldmatrix.sync.aligned.m8n8.x4.shared.b16 {%0,%1,%2,%3}, [%4];"
        : "=r"(r[0]), "=r"(r[1]), "=r"(r[2]), "=r"(r[3]) : "r"(addr));
}

__global__ __launch_bounds__(THREADS_B, 2) void atom_quadform_mma(
    const float* __restrict__ ps, int N, int numTiles)
{
    extern __shared__ char smem[];
    __nv_bfloat16* sA = reinterpret_cast<__nv_bfloat16*>(smem + OFF_A);
    float* sPart = reinterpret_cast<float*>(smem + OFF_SPART);
    float* sInv  = reinterpret_cast<float*>(smem + OFF_INV);
    const uint32_t* sBhi = reinterpret_cast<const uint32_t*>(smem + OFF_BHI);
    const uint32_t* sBlo = reinterpret_cast<const uint32_t*>(smem + OFF_BLO);

    const int tid = threadIdx.x;
    const int wid = tid >> 5;
    const int lid = tid & 31;
    const int g  = lid >> 2;
    const int tg = lid & 3;
    const int mrow0 = (wid & 3) * 32;
    const int ng    = wid >> 2;          // n column group (32 cols)

    const int arow  = tid >> 2;          // loader row 0..127
    const int apart = tid & 3;           // loader col chunk of 32

    // ldmatrix source address (per lane): tile t = lid/8, row-in-tile lid%8.
    const uint32_t smem_u32 = (uint32_t)__cvta_generic_to_shared(smem);
    const int lt = lid >> 3;             // 0..3
    const int lr = lid & 7;
    const uint32_t ldsm_base = smem_u32 + OFF_A
        + (uint32_t)(((mrow0 + (lt & 1) * 8 + lr) * A_STRIDE + (lt >> 1) * 8) * 2);

    // Stage packed B (tile-invariant) into smem once.
    {
        const uint4* srcH = reinterpret_cast<const uint4*>(g_Bhi_pack);
        const uint4* srcL = reinterpret_cast<const uint4*>(g_Blo_pack);
        uint4* dstH = reinterpret_cast<uint4*>(smem + OFF_BHI);
        uint4* dstL = reinterpret_cast<uint4*>(smem + OFF_BLO);
        for (int i = tid; i < 2048; i += THREADS_B) {
            dstH[i] = srcH[i];
            dstL[i] = srcL[i];
        }
    }
    __syncthreads();

    for (int tile = blockIdx.x; tile < numTiles; tile += gridDim.x) {
        const int base = tile * TILE_M;

        // ---- load phase: global ps -> bf16 A + inv ----
        {
            const int ga = base + arow;
            float ss = 0.f;
            #pragma unroll
            for (int q = 0; q < 8; q++) {
                const int col = apart * 32 + q * 4;
                float4 pv = make_float4(0.f, 0.f, 0.f, 0.f);
                if (ga < N)
                    pv = *reinterpret_cast<const float4*>(ps + (size_t)ga * DIMS + col);
                ss = fmaf(pv.x, pv.x, ss);
                ss = fmaf(pv.y, pv.y, ss);
                ss = fmaf(pv.z, pv.z, ss);
                ss = fmaf(pv.w, pv.w, ss);

                __nv_bfloat162 p01, p23;
                p01.x = __float2bfloat16_rn(pv.x);
                p01.y = __float2bfloat16_rn(pv.y);
                p23.x = __float2bfloat16_rn(pv.z);
                p23.y = __float2bfloat16_rn(pv.w);
                *reinterpret_cast<__nv_bfloat162*>(&sA[arow * A_STRIDE + col])     = p01;
                *reinterpret_cast<__nv_bfloat162*>(&sA[arow * A_STRIDE + col + 2]) = p23;
            }
            ss += __shfl_xor_sync(0xffffffffu, ss, 1);
            ss += __shfl_xor_sync(0xffffffffu, ss, 2);
            if (apart == 0) sInv[arow] = (ss > 0.f) ? 1.f / ss : 0.f;
        }
        __syncthreads();   // A/inv visible

        // ---- mma mainloop: acc = A * (Qhi + Qlo) ----
        float acc[2][4][4];
        #pragma unroll
        for (int mt = 0; mt < 2; mt++)
            #pragma unroll
            for (int nt = 0; nt < 4; nt++)
                #pragma unroll
                for (int c = 0; c < 4; c++) acc[mt][nt][c] = 0.f;

        #pragma unroll
        for (int u = 0; u < 8; u++) {
            uint32_t afrag[2][4];
            #pragma unroll
            for (int mt = 0; mt < 2; mt++)
                ldsm_x4(afrag[mt],
                        ldsm_base + (uint32_t)((mt * 16 * A_STRIDE + u * 16) * 2));
            #pragma unroll
            for (int nt = 0; nt < 4; nt++) {
                const int t = ng * 4 + nt;
                const int bidx = ((u * 16 + t) * 32 + lid) * 2;
                const uint2 bh = *reinterpret_cast<const uint2*>(sBhi + bidx);
                const uint2 bl = *reinterpret_cast<const uint2*>(sBlo + bidx);
                #pragma unroll
                for (int mt = 0; mt < 2; mt++) {
                    mma_bf16(acc[mt][nt], afrag[mt], bh.x, bh.y);
                    mma_bf16(acc[mt][nt], afrag[mt], bl.x, bl.y);
                }
            }
        }

        // ---- epilogue: partial = dot(2*ps - h, Y_row) over warp's 32 cols
        #pragma unroll
        for (int mt = 0; mt < 2; mt++) {
            const int r0 = mrow0 + mt * 16 + g;
            const int r1 = r0 + 8;
            const int gr0 = base + r0, gr1 = base + r1;
            float p0 = 0.f, p1 = 0.f;
            #pragma unroll
            for (int nt = 0; nt < 4; nt++) {
                const int c = ng * 32 + nt * 8 + tg * 2;
                float2 v0 = make_float2(0.f, 0.f), v1 = make_float2(0.f, 0.f);
                if (gr0 < N)
                    v0 = *reinterpret_cast<const float2*>(ps + (size_t)gr0 * DIMS + c);
                if (gr1 < N)
                    v1 = *reinterpret_cast<const float2*>(ps + (size_t)gr1 * DIMS + c);
                const __nv_bfloat162 h0 =
                    *reinterpret_cast<const __nv_bfloat162*>(&sA[r0 * A_STRIDE + c]);
                const __nv_bfloat162 h1 =
                    *reinterpret_cast<const __nv_bfloat162*>(&sA[r1 * A_STRIDE + c]);
                p0 = fmaf(2.f * v0.x - __bfloat162float(h0.x), acc[mt][nt][0], p0);
                p0 = fmaf(2.f * v0.y - __bfloat162float(h0.y), acc[mt][nt][1], p0);
                p1 = fmaf(2.f * v1.x - __bfloat162float(h1.x), acc[mt][nt][2], p1);
                p1 = fmaf(2.f * v1.y - __bfloat162float(h1.y), acc[mt][nt][3], p1);
            }
            p0 += __shfl_xor_sync(0xffffffffu, p0, 1);
            p0 += __shfl_xor_sync(0xffffffffu, p0, 2);
            p1 += __shfl_xor_sync(0xffffffffu, p1, 1);
            p1 += __shfl_xor_sync(0xffffffffu, p1, 2);
            if (tg == 0) {
                sPart[r0 * 4 + ng] = p0;
                sPart[r1 * 4 + ng] = p1;
            }
        }
        __syncthreads();   // sPart visible

        if (tid < TILE_M) {
            const float* pr = sPart + tid * 4;
            const float vv = ((pr[0] + pr[1]) + pr[2]) + pr[3];
            const int ga = base + tid;
            if (ga < N) g_atomval[ga] = vv * sInv[tid];
        }
        __syncthreads();   // all reads of A/sPart/sInv done before next store
    }
}

// ---------------------------------------------------------------------------
// Kernel C: segment sum using precomputed boundaries. One warp / structure.
// ---------------------------------------------------------------------------
__global__ void seg_sum(float* __restrict__ out, int S)
{
    const int s = blockIdx.x * (blockDim.x >> 5) + (threadIdx.x >> 5);
    if (s >= S) return;
    const int lane = threadIdx.x & 31;

    const int lo = g_start[s];
    const int hi = g_start[s + 1];

    float sum = 0.f;
    for (int i = lo + lane; i < hi; i += 32)
        sum += g_atomval[i];
    #pragma unroll
    for (int off = 16; off; off >>= 1)
        sum += __shfl_xor_sync(0xffffffffu, sum, off);
    if (lane == 0) out[s] = sum;
}

// ---------------------------------------------------------------------------
// Launch.
// ---------------------------------------------------------------------------
extern "C" void kernel_launch(void* const* d_in, const int* in_sizes, int n_in,
                              void* d_out, int out_size)
{
    const float* ps   = (const float*)d_in[0];
    const float* sp   = (const float*)d_in[1];
    const float* w    = (const float*)d_in[2];
    const int*   aseg = (const int*)d_in[3];
    const int*   sseg = (const int*)d_in[4];

    const int N = in_sizes[3];
    const int M = in_sizes[4];
    const int S = out_size;          // P == 1
    float* out = (float*)d_out;

    mark_starts<<<(N + 255) / 256, 256>>>(aseg, N, S);

    compute_Q_partial<<<QP_BLOCKS, 256>>>(sp, w, sseg, M);
    reduce_Q<<<DIMS * DIMS / 256, 256>>>();

    cudaFuncSetAttribute(atom_quadform_mma,
                         cudaFuncAttributeMaxDynamicSharedMemorySize, SMEM_TOTAL_B);
    const int numTiles = (N + TILE_M - 1) / TILE_M;
    const int grid = numTiles < 296 ? numTiles : 296;   // 2 CTAs/SM
    atom_quadform_mma<<<grid, THREADS_B, SMEM_TOTAL_B>>>(ps, N, numTiles);

    seg_sum<<<(S + 7) / 8, 256>>>(out, S);
}

// round 17
// speedup vs baseline: 1.0626x; 1.0626x over previous
#include <cuda_runtime.h>
#include <cuda_bf16.h>
#include <cstdint>
#include <cstddef>

// ---------------------------------------------------------------------------
// FullGapModel, specialized: D = 128, P = 1, zeta = 2.
// out[s] = sum_{atoms a in s} ps_a^T Q ps_a / ||ps_a||^2,
//   Q = sum_m w[seg_sup[m]] * sp_m sp_m^T  (128x128, symmetric).
// Main kernel: WARP-DECOUPLED bf16 mma.sync (m16n8k16). Each warp owns a
// 16-atom step end-to-end (private smem slice, no block barriers in the hot
// loop). Q split into bf16 hi+lo accumulated in f32; epilogue compensation
// val = dot(h + 2*delta, Y) / ||ps||^2 with delta = bf16(ps - h).
// ---------------------------------------------------------------------------

#define DIMS 128
constexpr int THREADS_B  = 512;     // 16 warps
constexpr int MAX_ATOMS  = 131072;  // >= N = 100000
constexpr int QP_BLOCKS  = 80;
constexpr int MAX_STRUCT = 8192;    // >= S = 2000

__device__ float    g_Qpart[QP_BLOCKS][DIMS * DIMS];
__device__ uint32_t g_Bhi_pack[8192];   // bf16x2 fragment-packed Q hi
__device__ uint32_t g_Blo_pack[8192];   // bf16x2 fragment-packed Q lo
__device__ float    g_atomval[MAX_ATOMS];
__device__ int      g_start[MAX_STRUCT + 1];

// ---------------------------------------------------------------------------
// Kernel A1: partial Q over M-chunks. Thread owns 8x8 register tile of Q.
// ---------------------------------------------------------------------------
__global__ __launch_bounds__(256) void compute_Q_partial(
    const float* __restrict__ sp,
    const float* __restrict__ weights,
    const int*   __restrict__ supseg,
    int M)
{
    __shared__ float srow[8][DIMS];
    __shared__ float sw[8];

    const int chunk = (M + QP_BLOCKS - 1) / QP_BLOCKS;
    const int m_lo = blockIdx.x * chunk;
    const int m_hi = min(M, m_lo + chunk);

    const int i0 = (threadIdx.x >> 4) * 8;
    const int j0 = (threadIdx.x & 15) * 8;

    float acc[8][8];
    #pragma unroll
    for (int a = 0; a < 8; a++)
        #pragma unroll
        for (int b = 0; b < 8; b++) acc[a][b] = 0.f;

    for (int m0 = m_lo; m0 < m_hi; m0 += 8) {
        const int rows = min(8, m_hi - m0);
        __syncthreads();
        for (int idx = threadIdx.x; idx < rows * DIMS; idx += 256)
            srow[idx >> 7][idx & 127] = sp[(size_t)m0 * DIMS + idx];
        if (threadIdx.x < rows)
            sw[threadIdx.x] = weights[supseg[m0 + threadIdx.x]];
        __syncthreads();

        #pragma unroll 8
        for (int u = 0; u < rows; u++) {
            float si[8], sj[8];
            *reinterpret_cast<float4*>(&si[0]) = *reinterpret_cast<float4*>(&srow[u][i0]);
            *reinterpret_cast<float4*>(&si[4]) = *reinterpret_cast<float4*>(&srow[u][i0 + 4]);
            *reinterpret_cast<float4*>(&sj[0]) = *reinterpret_cast<float4*>(&srow[u][j0]);
            *reinterpret_cast<float4*>(&sj[4]) = *reinterpret_cast<float4*>(&srow[u][j0 + 4]);
            const float wu = sw[u];
            #pragma unroll
            for (int a = 0; a < 8; a++) {
                const float siw = wu * si[a];
                #pragma unroll
                for (int b = 0; b < 8; b++)
                    acc[a][b] = fmaf(siw, sj[b], acc[a][b]);
            }
        }
    }

    float* dst = g_Qpart[blockIdx.x];
    #pragma unroll
    for (int a = 0; a < 8; a++)
        #pragma unroll
        for (int b = 0; b < 8; b += 4)
            *reinterpret_cast<float4*>(&dst[(i0 + a) * DIMS + j0 + b]) =
                *reinterpret_cast<float4*>(&acc[a][b]);
}

// ---------------------------------------------------------------------------
// Kernel A2: reduce partials; emit bf16 hi/lo Q in mma fragment-packed order.
// For element (n, k): B-frag of tile (t = n/8, u = k/16) at lane
// l = (n%8)*4 + ((k%8)>>1), reg r = (k%16)/8, halfword = k&1.
// ---------------------------------------------------------------------------
__global__ void reduce_Q()
{
    const int idx = blockIdx.x * blockDim.x + threadIdx.x;   // 0..16383
    const int n = idx >> 7, k = idx & 127;
    float s = 0.f;
    #pragma unroll 8
    for (int p = 0; p < QP_BLOCKS; p++)
        s += g_Qpart[p][idx];

    const __nv_bfloat16 hi = __float2bfloat16_rn(s);
    const __nv_bfloat16 lo = __float2bfloat16_rn(s - __bfloat162float(hi));

    const int u = k >> 4, t = n >> 3;
    const int g = n & 7, kk = k & 15;
    const int r = kk >> 3, tg = (kk & 7) >> 1, half = kk & 1;
    const int u32idx = ((u * 16 + t) * 32 + (g * 4 + tg)) * 2 + r;

    reinterpret_cast<__nv_bfloat16*>(g_Bhi_pack)[u32idx * 2 + half] = hi;
    reinterpret_cast<__nv_bfloat16*>(g_Blo_pack)[u32idx * 2 + half] = lo;
}

// ---------------------------------------------------------------------------
// Kernel D: structure boundaries from the sorted atom_segments array.
// ---------------------------------------------------------------------------
__global__ void mark_starts(const int* __restrict__ aseg, int N, int S)
{
    const int i = blockIdx.x * blockDim.x + threadIdx.x;
    if (i >= N) return;
    const int cur = aseg[i];
    const int prev = (i == 0) ? -1 : aseg[i - 1];
    for (int s = prev + 1; s <= cur; s++) g_start[s] = i;
    if (i == N - 1)
        for (int s = cur + 1; s <= S; s++) g_start[s] = N;
}

// ---------------------------------------------------------------------------
// Kernel B: warp-decoupled HMMA quadratic form.
// smem: Bhi/Blo packed (64 KB, read-only after one __syncthreads), then
// 16 warp-private slices of 8768 B: h (16x136 bf16), delta (16x136 bf16),
// inv (16 f32).
// ---------------------------------------------------------------------------
constexpr int A_STRIDE     = 136;                  // bf16 units (272 B rows)
constexpr int OFF_BHI      = 0;                    // 32768 B
constexpr int OFF_BLO      = 32768;                // 32768 B
constexpr int OFF_SL       = 65536;
constexpr int SL_H         = 0;                    // 16*136*2 = 4352 B
constexpr int SL_D         = 4352;                 // 4352 B
constexpr int SL_INV       = 8704;                 // 64 B
constexpr int SLICE_BYTES  = 8768;
constexpr int SMEM_TOTAL_B = OFF_SL + 16 * SLICE_BYTES;   // 205824 B

__device__ __forceinline__ void mma_bf16(float* d, const uint32_t* a,
                                         uint32_t b0, uint32_t b1) {
    asm volatile(
        "mma.sync.aligned.m16n8k16.row.col.f32.bf16.bf16.f32 "
        "{%0,%1,%2,%3}, {%4,%5,%6,%7}, {%8,%9}, {%0,%1,%2,%3};"
        : "+f"(d[0]), "+f"(d[1]), "+f"(d[2]), "+f"(d[3])
        : "r"(a[0]), "r"(a[1]), "r"(a[2]), "r"(a[3]), "r"(b0), "r"(b1));
}

__device__ __forceinline__ void ldsm_x4(uint32_t* r, uint32_t addr) {
    asm volatile(
        "ldmatrix.sync.aligned.m8n8.x4.shared.b16 {%0,%1,%2,%3}, [%4];"
        : "=r"(r[0]), "=r"(r[1]), "=r"(r[2]), "=r"(r[3]) : "r"(addr));
}

__global__ __launch_bounds__(THREADS_B, 1) void atom_quadform_mma(
    const float* __restrict__ ps, int N, int numSteps, int totalWarps)
{
    extern __shared__ char smem[];
    const int tid = threadIdx.x;
    const int wid = tid >> 5;
    const int lid = tid & 31;

    const uint32_t smem_u32 = (uint32_t)__cvta_generic_to_shared(smem);
    char* slice = smem + OFF_SL + wid * SLICE_BYTES;
    __nv_bfloat16* sH   = reinterpret_cast<__nv_bfloat16*>(slice + SL_H);
    __nv_bfloat16* sD   = reinterpret_cast<__nv_bfloat16*>(slice + SL_D);
    float*         sInv = reinterpret_cast<float*>(slice + SL_INV);
    const uint32_t* sBhi = reinterpret_cast<const uint32_t*>(smem + OFF_BHI);
    const uint32_t* sBlo = reinterpret_cast<const uint32_t*>(smem + OFF_BLO);

    // Stage packed B into smem once (only block barrier in the kernel).
    {
        const uint4* srcH = reinterpret_cast<const uint4*>(g_Bhi_pack);
        const uint4* srcL = reinterpret_cast<const uint4*>(g_Blo_pack);
        uint4* dstH = reinterpret_cast<uint4*>(smem + OFF_BHI);
        uint4* dstL = reinterpret_cast<uint4*>(smem + OFF_BLO);
        for (int i = tid; i < 2048; i += THREADS_B) {
            dstH[i] = srcH[i];
            dstL[i] = srcL[i];
        }
    }
    __syncthreads();

    // Lane roles.
    const int g  = lid >> 2;            // 0..7  (epilogue row group)
    const int tg = lid & 3;             // 0..3
    const int lrow = lid >> 1;          // 0..15 (load row)
    const int hf   = lid & 1;           // row half (64 floats)

    // ldmatrix per-lane source address (warp-local 16 rows).
    const int lt = lid >> 3, lr = lid & 7;
    const uint32_t slice_u32 = smem_u32 + OFF_SL + (uint32_t)(wid * SLICE_BYTES);
    const uint32_t ldsm_base = slice_u32 +
        (uint32_t)((((lt & 1) * 8 + lr) * A_STRIDE + (lt >> 1) * 8) * 2);

    const int gwarp = blockIdx.x * (THREADS_B / 32) + wid;

    for (int step = gwarp; step < numSteps; step += totalWarps) {
        const int gbase = step * 16;
        __syncwarp();   // previous step's slice reads complete

        // ---- load phase: 16 rows -> bf16 h + bf16 delta + inv ----
        {
            const int ga = gbase + lrow;
            float ss = 0.f;
            #pragma unroll
            for (int q = 0; q < 16; q++) {
                const int col = hf * 64 + q * 4;
                float4 v = make_float4(0.f, 0.f, 0.f, 0.f);
                if (ga < N)
                    v = *reinterpret_cast<const float4*>(ps + (size_t)ga * DIMS + col);
                ss = fmaf(v.x, v.x, ss);
                ss = fmaf(v.y, v.y, ss);
                ss = fmaf(v.z, v.z, ss);
                ss = fmaf(v.w, v.w, ss);

                float2 v01 = make_float2(v.x, v.y);
                float2 v23 = make_float2(v.z, v.w);
                __nv_bfloat162 h01 = __float22bfloat162_rn(v01);
                __nv_bfloat162 h23 = __float22bfloat162_rn(v23);
                float2 d01 = make_float2(v.x - __bfloat162float(h01.x),
                                         v.y - __bfloat162float(h01.y));
                float2 d23 = make_float2(v.z - __bfloat162float(h23.x),
                                         v.w - __bfloat162float(h23.y));
                __nv_bfloat162 e01 = __float22bfloat162_rn(d01);
                __nv_bfloat162 e23 = __float22bfloat162_rn(d23);

                uint2 hp, dp;
                hp.x = *reinterpret_cast<uint32_t*>(&h01);
                hp.y = *reinterpret_cast<uint32_t*>(&h23);
                dp.x = *reinterpret_cast<uint32_t*>(&e01);
                dp.y = *reinterpret_cast<uint32_t*>(&e23);
                *reinterpret_cast<uint2*>(&sH[lrow * A_STRIDE + col]) = hp;
                *reinterpret_cast<uint2*>(&sD[lrow * A_STRIDE + col]) = dp;
            }
            ss += __shfl_xor_sync(0xffffffffu, ss, 1);
            if (hf == 0) sInv[lrow] = (ss > 0.f) ? 1.f / ss : 0.f;
        }
        __syncwarp();   // slice writes visible to all lanes

        // ---- A fragments for all 8 k-groups (reused across both n-halves)
        uint32_t afrag[8][4];
        #pragma unroll
        for (int u = 0; u < 8; u++)
            ldsm_x4(afrag[u], ldsm_base + (uint32_t)(u * 32));

        float pr0 = 0.f, pr1 = 0.f;   // dot partials, rows g and g+8

        #pragma unroll
        for (int half = 0; half < 2; half++) {
            float acc[8][4];
            #pragma unroll
            for (int nt = 0; nt < 8; nt++)
                #pragma unroll
                for (int c = 0; c < 4; c++) acc[nt][c] = 0.f;

            #pragma unroll
            for (int u = 0; u < 8; u++) {
                #pragma unroll
                for (int nt = 0; nt < 8; nt++) {
                    const int t = half * 8 + nt;
                    const int bidx = ((u * 16 + t) * 32 + lid) * 2;
                    const uint2 bh = *reinterpret_cast<const uint2*>(sBhi + bidx);
                    const uint2 bl = *reinterpret_cast<const uint2*>(sBlo + bidx);
                    mma_bf16(acc[nt], afrag[u], bh.x, bh.y);
                    mma_bf16(acc[nt], afrag[u], bl.x, bl.y);
                }
            }

            // epilogue for this half: E = h + 2*delta from the slice
            #pragma unroll
            for (int nt = 0; nt < 8; nt++) {
                const int t = half * 8 + nt;
                const int c = t * 8 + tg * 2;
                const __nv_bfloat162 h0 =
                    *reinterpret_cast<const __nv_bfloat162*>(&sH[g * A_STRIDE + c]);
                const __nv_bfloat162 d0 =
                    *reinterpret_cast<const __nv_bfloat162*>(&sD[g * A_STRIDE + c]);
                const __nv_bfloat162 h1 =
                    *reinterpret_cast<const __nv_bfloat162*>(&sH[(g + 8) * A_STRIDE + c]);
                const __nv_bfloat162 d1 =
                    *reinterpret_cast<const __nv_bfloat162*>(&sD[(g + 8) * A_STRIDE + c]);

                const float e0x = __bfloat162float(h0.x) + 2.f * __bfloat162float(d0.x);
                const float e0y = __bfloat162float(h0.y) + 2.f * __bfloat162float(d0.y);
                const float e1x = __bfloat162float(h1.x) + 2.f * __bfloat162float(d1.x);
                const float e1y = __bfloat162float(h1.y) + 2.f * __bfloat162float(d1.y);

                pr0 = fmaf(e0x, acc[nt][0], pr0);
                pr0 = fmaf(e0y, acc[nt][1], pr0);
                pr1 = fmaf(e1x, acc[nt][2], pr1);
                pr1 = fmaf(e1y, acc[nt][3], pr1);
            }
        }

        // ---- reduce across the 4 tg lanes; write 2 atoms per lane group ----
        pr0 += __shfl_xor_sync(0xffffffffu, pr0, 1);
        pr0 += __shfl_xor_sync(0xffffffffu, pr0, 2);
        pr1 += __shfl_xor_sync(0xffffffffu, pr1, 1);
        pr1 += __shfl_xor_sync(0xffffffffu, pr1, 2);
        if (tg == 0) {
            const int ga0 = gbase + g;
            const int ga1 = gbase + g + 8;
            if (ga0 < N) g_atomval[ga0] = pr0 * sInv[g];
            if (ga1 < N) g_atomval[ga1] = pr1 * sInv[g + 8];
        }
    }
}

// ---------------------------------------------------------------------------
// Kernel C: segment sum using precomputed boundaries. One warp / structure.
// ---------------------------------------------------------------------------
__global__ void seg_sum(float* __restrict__ out, int S)
{
    const int s = blockIdx.x * (blockDim.x >> 5) + (threadIdx.x >> 5);
    if (s >= S) return;
    const int lane = threadIdx.x & 31;

    const int lo = g_start[s];
    const int hi = g_start[s + 1];

    float sum = 0.f;
    for (int i = lo + lane; i < hi; i += 32)
        sum += g_atomval[i];
    #pragma unroll
    for (int off = 16; off; off >>= 1)
        sum += __shfl_xor_sync(0xffffffffu, sum, off);
    if (lane == 0) out[s] = sum;
}

// ---------------------------------------------------------------------------
// Launch.
// ---------------------------------------------------------------------------
extern "C" void kernel_launch(void* const* d_in, const int* in_sizes, int n_in,
                              void* d_out, int out_size)
{
    const float* ps   = (const float*)d_in[0];
    const float* sp   = (const float*)d_in[1];
    const float* w    = (const float*)d_in[2];
    const int*   aseg = (const int*)d_in[3];
    const int*   sseg = (const int*)d_in[4];

    const int N = in_sizes[3];
    const int M = in_sizes[4];
    const int S = out_size;          // P == 1
    float* out = (float*)d_out;

    mark_starts<<<(N + 255) / 256, 256>>>(aseg, N, S);

    compute_Q_partial<<<QP_BLOCKS, 256>>>(sp, w, sseg, M);
    reduce_Q<<<DIMS * DIMS / 256, 256>>>();

    cudaFuncSetAttribute(atom_quadform_mma,
                         cudaFuncAttributeMaxDynamicSharedMemorySize, SMEM_TOTAL_B);
    const int numSteps = (N + 15) / 16;
    const int grid = 148;
    const int totalWarps = grid * (THREADS_B / 32);
    atom_quadform_mma<<<grid, THREADS_B, SMEM_TOTAL_B>>>(ps, N, numSteps, totalWarps);

    seg_sum<<<(S + 7) / 8, 256>>>(out, S);
}